// round 6
// baseline (speedup 1.0000x reference)
#include <cuda_runtime.h>
#include <cstdint>

#define DEV_INLINE __device__ __forceinline__

// Arch-specific (sm_103a/sm_100a) feature gate: tcgen05 is only legal in the
// arch-specific compilation pass. The portable compute_103 PTX pass compiles
// the SIMT fallback below instead (never executed when the sm_103a cubin is
// loaded, but keeps ptxas happy and provides a correct safety net).
#if defined(__CUDA_ARCH_FEAT_SM103_ALL) || defined(__CUDA_ARCH_FEAT_SM101_ALL) || \
    defined(__CUDA_ARCH_FEAT_SM100_ALL) || defined(__CUDA_ARCH_SPECIFIC__)
#define HAS_TCGEN05 1
#else
#define HAS_TCGEN05 0
#endif

// ---------------- problem sizes ----------------
#define BATCH 16384
#define DIN   1024
#define DHID  1024
#define DOUT  512
#define KDIM  6144          // 6 feature planes x 1024
#define LN_EPSF 1e-5f

// ---------------- scratch (static device globals; no allocation) ----------------
__device__ float g_E1[(size_t)BATCH * KDIM];   // expanded features layer1 (tf32-rounded fp32)
__device__ float g_E2[(size_t)BATCH * KDIM];   // expanded features layer2
__device__ float g_H [(size_t)BATCH * DHID];   // raw layer-1 output
__device__ float g_W1p[(size_t)DHID * KDIM];   // packed weights layer1
__device__ float g_W2p[(size_t)DOUT * KDIM];   // packed weights layer2
__device__ float g_b1e[DHID];                  // bias1 + sum_i coeff1[o,i,0]
__device__ float g_b2e[DOUT];

// ---------------- small helpers ----------------
DEV_INLINE uint32_t smem_u32(const void* p) {
    uint32_t a;
    asm("{ .reg .u64 t; cvta.to.shared.u64 t, %1; cvt.u32.u64 %0, t; }" : "=r"(a) : "l"(p));
    return a;
}
DEV_INLINE float to_tf32(float x) {          // round-to-nearest tf32, stored as fp32
    uint32_t r;
    asm("cvt.rna.tf32.f32 %0, %1;" : "=r"(r) : "f"(x));
    return __uint_as_float(r);
}
DEV_INLINE float warp_sum(float v) {
#pragma unroll
    for (int o = 16; o > 0; o >>= 1) v += __shfl_xor_sync(0xffffffffu, v, o);
    return v;
}
DEV_INLINE uint32_t sw128(uint32_t off) { return off ^ ((off >> 3) & 0x70); }

#if HAS_TCGEN05
DEV_INLINE uint32_t elect_one() {
    uint32_t p;
    asm volatile("{ .reg .pred p; elect.sync _|p, 0xFFFFFFFF; selp.b32 %0, 1, 0, p; }" : "=r"(p));
    return p;
}

#define MBAR_INIT(addr, cnt) \
    asm volatile("mbarrier.init.shared.b64 [%0], %1;" :: "r"(addr), "r"(cnt) : "memory")

DEV_INLINE void mbar_wait(uint32_t mbar, uint32_t parity) {
    asm volatile(
        "{\n\t.reg .pred P;\n\t"
        "WL_%=:\n\t"
        "mbarrier.try_wait.parity.acquire.cta.shared::cta.b64 P, [%0], %1, 0x989680;\n\t"
        "@P bra WD_%=;\n\t"
        "bra WL_%=;\n\t"
        "WD_%=:\n\t}"
        :: "r"(mbar), "r"(parity) : "memory");
}

#define TCG_ALLOC(smaddr, n) \
    asm volatile("tcgen05.alloc.cta_group::1.sync.aligned.shared::cta.b32 [%0], %1;" \
                 :: "r"(smaddr), "r"(n) : "memory")
#define TCG_RELINQ() \
    asm volatile("tcgen05.relinquish_alloc_permit.cta_group::1.sync.aligned;")
#define TCG_DEALLOC(t, n) \
    asm volatile("tcgen05.dealloc.cta_group::1.sync.aligned.b32 %0, %1;" :: "r"(t), "r"(n))
#define TCG_COMMIT(mb) \
    asm volatile("tcgen05.commit.cta_group::1.mbarrier::arrive::one.shared::cluster.b64 [%0];" \
                 :: "r"(mb) : "memory")
#define TCG_FENCE_AFTER() \
    asm volatile("tcgen05.fence::after_thread_sync;" ::: "memory")
#define TCG_WAIT_LD() \
    asm volatile("tcgen05.wait::ld.sync.aligned;" ::: "memory")
#define FENCE_ASYNC() \
    asm volatile("fence.proxy.async.shared::cta;" ::: "memory")

DEV_INLINE void tmem_ld16(uint32_t* r, uint32_t addr) {
    asm volatile("tcgen05.ld.sync.aligned.32x32b.x16.b32 "
        "{%0,%1,%2,%3,%4,%5,%6,%7,%8,%9,%10,%11,%12,%13,%14,%15}, [%16];"
        : "=r"(r[0]), "=r"(r[1]), "=r"(r[2]), "=r"(r[3]),
          "=r"(r[4]), "=r"(r[5]), "=r"(r[6]), "=r"(r[7]),
          "=r"(r[8]), "=r"(r[9]), "=r"(r[10]), "=r"(r[11]),
          "=r"(r[12]), "=r"(r[13]), "=r"(r[14]), "=r"(r[15])
        : "r"(addr));
}

// tf32 SS MMA, cta_group::1: D[128,128] += A_smem[128,8] * B_smem[128,8]^T
DEV_INLINE void mma_tf32_ss(uint32_t d_tmem, uint64_t a_desc, uint64_t b_desc,
                            uint32_t idesc, uint32_t en) {
    asm volatile(
        "{\n\t.reg .pred p;\n\t"
        "setp.ne.u32 p, %5, 0;\n\t"
        "tcgen05.mma.cta_group::1.kind::tf32 [%0], %1, %2, %3, {%4,%4,%4,%4}, p;\n\t}"
        :: "r"(d_tmem), "l"(a_desc), "l"(b_desc), "r"(idesc), "r"(0u), "r"(en)
        : "memory");
}

// SW128 K-major SMEM descriptor (layout=2, version=1, SBO=64, LBO=1).
// NOTE: the base constant lives inside the function (function-local) — a
// namespace-scope __device__ constexpr here breaks the host registration stub
// because the host pass compiles with HAS_TCGEN05 == 0.
DEV_INLINE unsigned long long make_desc(uint32_t smaddr) {
    const unsigned long long base =
        (2ull << 61) | (1ull << 46) | (64ull << 32) | (1ull << 16);
    return base | ((unsigned long long)(smaddr >> 4) & 0x3FFFull);
}
#endif  // HAS_TCGEN05

// ---------------- weight packing ----------------
// coeff: [O, 1024, 6] ; bw: [O, 1024] ; Wp: [O, 6144] (plane p = degree p+1, plane 5 = base_w)
__global__ __launch_bounds__(256) void pack_w_kernel(const float* __restrict__ coeff,
                                                     const float* __restrict__ bw,
                                                     float* __restrict__ Wp) {
    int idx = blockIdx.x * 256 + threadIdx.x;   // o*1024 + i
    int o = idx >> 10, i = idx & 1023;
    const float* c = coeff + (size_t)idx * 6;
    float* row = Wp + (size_t)o * KDIM;
    row[0 * 1024 + i] = to_tf32(c[1]);
    row[1 * 1024 + i] = to_tf32(c[2]);
    row[2 * 1024 + i] = to_tf32(c[3]);
    row[3 * 1024 + i] = to_tf32(c[4]);
    row[4 * 1024 + i] = to_tf32(c[5]);
    row[5 * 1024 + i] = to_tf32(bw[idx]);
}

// bias_eff[o] = bias[o] + sum_i coeff[o,i,0]   (T0 == 1 contribution)
__global__ __launch_bounds__(128) void bias_eff_kernel(const float* __restrict__ coeff,
                                                       const float* __restrict__ bias,
                                                       float* __restrict__ out) {
    int o = blockIdx.x, tid = threadIdx.x;
    const float* c = coeff + (size_t)o * 1024 * 6;
    float s = 0.f;
    for (int i = tid; i < 1024; i += 128) s += c[(size_t)i * 6];
    s = warp_sum(s);
    __shared__ float red[4];
    if ((tid & 31) == 0) red[tid >> 5] = s;
    __syncthreads();
    if (tid == 0) out[o] = bias[o] + red[0] + red[1] + red[2] + red[3];
}

// ---------------- feature expansion, layer 1 ----------------
// u = tanh(x); t = tanh(u); planes = [T1..T5(t), u]
__global__ __launch_bounds__(256) void expand1_kernel(const float* __restrict__ x,
                                                      float* __restrict__ E) {
    int idx = blockIdx.x * 256 + threadIdx.x;
    int b = idx >> 10, i = idx & 1023;
    float u = tanhf(x[idx]);
    float t = tanhf(u);
    float T2 = 2.f * t * t - 1.f;
    float T3 = 2.f * t * T2 - t;
    float T4 = 2.f * t * T3 - T2;
    float T5 = 2.f * t * T4 - T3;
    float* row = E + (size_t)b * KDIM;
    row[i]        = to_tf32(t);
    row[1024 + i] = to_tf32(T2);
    row[2048 + i] = to_tf32(T3);
    row[3072 + i] = to_tf32(T4);
    row[4096 + i] = to_tf32(T5);
    row[5120 + i] = to_tf32(u);
}

// ---------------- LayerNorm + SiLU + feature expansion, layer 2 ----------------
__global__ __launch_bounds__(256) void ln_silu_expand_kernel(const float* __restrict__ H,
                                                             const float* __restrict__ gamma,
                                                             const float* __restrict__ beta,
                                                             float* __restrict__ E) {
    int b = blockIdx.x, tid = threadIdx.x;
    int wid = tid >> 5, lane = tid & 31;
    float4 h = ((const float4*)(H + (size_t)b * DHID))[tid];
    float s = h.x + h.y + h.z + h.w;
    float q = h.x * h.x + h.y * h.y + h.z * h.z + h.w * h.w;
    s = warp_sum(s);
    q = warp_sum(q);
    __shared__ float red[16];
    if (lane == 0) { red[wid] = s; red[8 + wid] = q; }
    __syncthreads();
    if (wid == 0) {
        float a = (lane < 8) ? red[lane] : 0.f;
        float c = (lane < 8) ? red[8 + lane] : 0.f;
        a = warp_sum(a);
        c = warp_sum(c);
        if (lane == 0) { red[0] = a; red[1] = c; }
    }
    __syncthreads();
    float mean = red[0] * (1.f / 1024.f);
    float var  = red[1] * (1.f / 1024.f) - mean * mean;
    float rstd = rsqrtf(var + LN_EPSF);
    float4 gv = ((const float4*)gamma)[tid];
    float4 bv = ((const float4*)beta)[tid];
    float hh[4] = {h.x, h.y, h.z, h.w};
    float gg[4] = {gv.x, gv.y, gv.z, gv.w};
    float bb[4] = {bv.x, bv.y, bv.z, bv.w};
    float o1[4], o2[4], o3[4], o4[4], o5[4], o6[4];
#pragma unroll
    for (int j = 0; j < 4; j++) {
        float g  = (hh[j] - mean) * rstd * gg[j] + bb[j];
        float si = g * (1.f / (1.f + __expf(-g)));     // SiLU
        float t  = tanhf(si);
        float T2 = 2.f * t * t - 1.f;
        float T3 = 2.f * t * T2 - t;
        float T4 = 2.f * t * T3 - T2;
        float T5 = 2.f * t * T4 - T3;
        o1[j] = to_tf32(t);  o2[j] = to_tf32(T2); o3[j] = to_tf32(T3);
        o4[j] = to_tf32(T4); o5[j] = to_tf32(T5); o6[j] = to_tf32(si);
    }
    float* rowb = E + (size_t)b * KDIM + tid * 4;
    *(float4*)(rowb + 0)    = make_float4(o1[0], o1[1], o1[2], o1[3]);
    *(float4*)(rowb + 1024) = make_float4(o2[0], o2[1], o2[2], o2[3]);
    *(float4*)(rowb + 2048) = make_float4(o3[0], o3[1], o3[2], o3[3]);
    *(float4*)(rowb + 3072) = make_float4(o4[0], o4[1], o4[2], o4[3]);
    *(float4*)(rowb + 4096) = make_float4(o5[0], o5[1], o5[2], o5[3]);
    *(float4*)(rowb + 5120) = make_float4(o6[0], o6[1], o6[2], o6[3]);
}

// ---------------- GEMM: C[M,N] = A[M,K] * B[N,K]^T + bias ----------------
// sm_103a path: tf32 tcgen05, 128x128 tile, BK=32 (4 MMAs of K=8), SW128 K-major.
// portable path: SIMT FFMA fallback (same symbol; only runs if no arch cubin).
#if HAS_TCGEN05
__global__ __launch_bounds__(256, 4) void gemm_tf32_kernel(
    const float* __restrict__ A, const float* __restrict__ Bw,
    const float* __restrict__ bias, float* __restrict__ C,
    int M, int N, int K) {
    __shared__ __align__(1024) float sA[128 * 32];   // 16 KB
    __shared__ __align__(1024) float sB[128 * 32];   // 16 KB
    __shared__ __align__(16) uint32_t s_tmem[4];
    __shared__ __align__(8)  unsigned long long s_mbar;

    const int tid = threadIdx.x;
    const int wid = tid >> 5, lane = tid & 31;
    const int m0 = blockIdx.y * 128, n0 = blockIdx.x * 128;

    const uint32_t mbar = smem_u32(&s_mbar);
    if (tid == 0) MBAR_INIT(mbar, 1);
    if (wid == 0) {
        TCG_ALLOC(smem_u32(s_tmem), 128);
        TCG_RELINQ();
    }
    __syncthreads();
    uint32_t tmem;
    asm volatile("ld.shared.b32 %0, [%1];" : "=r"(tmem) : "r"(smem_u32(s_tmem)));

    const uint32_t aBase = smem_u32(sA), bBase = smem_u32(sB);
    // idesc: f32 accum, tf32 A/B, N=128, M=128, no transpose
    const uint32_t IDESC = (1u << 4) | (2u << 7) | (2u << 10) |
                           ((128u / 8) << 17) | ((128u / 16) << 24);

    const int KT = K >> 5;   // K/32
    for (int kt = 0; kt < KT; ++kt) {
        // issue this tile's global loads BEFORE waiting on the previous MMA
        const float* ga = A  + (size_t)m0 * K + (size_t)kt * 32;
        const float* gb = Bw + (size_t)n0 * K + (size_t)kt * 32;
        float4 va[4], vb[4];
#pragma unroll
        for (int p = 0; p < 4; p++) {
            int idx = tid + p * 256;          // 0..1023
            int r = idx >> 3, c4 = idx & 7;
            va[p] = *(const float4*)(ga + (size_t)r * K + (c4 << 2));
            vb[p] = *(const float4*)(gb + (size_t)r * K + (c4 << 2));
        }
        if (kt) mbar_wait(mbar, (kt - 1) & 1);   // previous MMA finished reading SMEM
#pragma unroll
        for (int p = 0; p < 4; p++) {
            int idx = tid + p * 256;
            int r = idx >> 3, c4 = idx & 7;
            uint32_t off = sw128((uint32_t)((r << 7) + (c4 << 4)));
            *(float4*)((char*)sA + off) = va[p];
            *(float4*)((char*)sB + off) = vb[p];
        }
        __syncthreads();
        if (wid == 0 && elect_one()) {
            FENCE_ASYNC();
            unsigned long long ad = make_desc(aBase);
            unsigned long long bd = make_desc(bBase);
#pragma unroll
            for (int s = 0; s < 4; s++)       // K=8 per MMA, +32B = +2 desc units per step
                mma_tf32_ss(tmem, ad + 2ull * s, bd + 2ull * s, IDESC, (kt | s) != 0);
            TCG_COMMIT(mbar);
        }
    }
    mbar_wait(mbar, (KT - 1) & 1);
    TCG_FENCE_AFTER();

    // epilogue: first warpgroup reads TMEM (each warp = its own 32 rows), adds bias, stores
    if (tid < 128) {
        int row = m0 + wid * 32 + lane;
        float* crow = C + (size_t)row * N + n0;
#pragma unroll 1
        for (int c0 = 0; c0 < 128; c0 += 16) {
            uint32_t r[16];
            tmem_ld16(r, tmem + (uint32_t)c0);
            TCG_WAIT_LD();
#pragma unroll
            for (int j = 0; j < 4; j++) {
                float4 v;
                v.x = __uint_as_float(r[4 * j + 0]) + __ldg(&bias[n0 + c0 + 4 * j + 0]);
                v.y = __uint_as_float(r[4 * j + 1]) + __ldg(&bias[n0 + c0 + 4 * j + 1]);
                v.z = __uint_as_float(r[4 * j + 2]) + __ldg(&bias[n0 + c0 + 4 * j + 2]);
                v.w = __uint_as_float(r[4 * j + 3]) + __ldg(&bias[n0 + c0 + 4 * j + 3]);
                *(float4*)(crow + c0 + 4 * j) = v;
            }
        }
    }
    __syncthreads();
    if (wid == 0) TCG_DEALLOC(tmem, 128);
}
#else  // ---------------- portable SIMT fallback ----------------
__global__ __launch_bounds__(256) void gemm_tf32_kernel(
    const float* __restrict__ A, const float* __restrict__ Bw,
    const float* __restrict__ bias, float* __restrict__ C,
    int M, int N, int K) {
    __shared__ float sA[128 * 33];
    __shared__ float sB[128 * 33];
    const int tid = threadIdx.x;
    const int m0 = blockIdx.y * 128, n0 = blockIdx.x * 128;
    const int tx = tid & 15, ty = tid >> 4;          // 16x16 thread grid, 8x8 micro-tile

    float acc[8][8];
#pragma unroll
    for (int i = 0; i < 8; i++)
#pragma unroll
        for (int j = 0; j < 8; j++) acc[i][j] = 0.f;

    for (int kt = 0; kt < (K >> 5); ++kt) {
        const float* ga = A  + (size_t)m0 * K + (size_t)kt * 32;
        const float* gb = Bw + (size_t)n0 * K + (size_t)kt * 32;
#pragma unroll
        for (int p = 0; p < 4; p++) {
            int idx = tid + p * 256;
            int r = idx >> 3, c = (idx & 7) << 2;
            float4 va = *(const float4*)(ga + (size_t)r * K + c);
            float4 vb = *(const float4*)(gb + (size_t)r * K + c);
            sA[r * 33 + c] = va.x; sA[r * 33 + c + 1] = va.y;
            sA[r * 33 + c + 2] = va.z; sA[r * 33 + c + 3] = va.w;
            sB[r * 33 + c] = vb.x; sB[r * 33 + c + 1] = vb.y;
            sB[r * 33 + c + 2] = vb.z; sB[r * 33 + c + 3] = vb.w;
        }
        __syncthreads();
#pragma unroll
        for (int kk = 0; kk < 32; kk++) {
            float a[8], b[8];
#pragma unroll
            for (int i = 0; i < 8; i++) a[i] = sA[(ty * 8 + i) * 33 + kk];
#pragma unroll
            for (int j = 0; j < 8; j++) b[j] = sB[(tx * 8 + j) * 33 + kk];
#pragma unroll
            for (int i = 0; i < 8; i++)
#pragma unroll
                for (int j = 0; j < 8; j++) acc[i][j] += a[i] * b[j];
        }
        __syncthreads();
    }
#pragma unroll
    for (int i = 0; i < 8; i++) {
        float* crow = C + (size_t)(m0 + ty * 8 + i) * N + n0 + tx * 8;
#pragma unroll
        for (int j = 0; j < 8; j++) crow[j] = acc[i][j] + bias[n0 + tx * 8 + j];
    }
}
#endif  // HAS_TCGEN05

// ---------------- launch ----------------
extern "C" void kernel_launch(void* const* d_in, const int* in_sizes, int n_in,
                              void* d_out, int out_size) {
    (void)in_sizes; (void)n_in; (void)out_size;
    const float* x     = (const float*)d_in[0];
    const float* c1    = (const float*)d_in[1];
    const float* bw1   = (const float*)d_in[2];
    const float* b1    = (const float*)d_in[3];
    const float* gamma = (const float*)d_in[4];
    const float* beta  = (const float*)d_in[5];
    const float* c2    = (const float*)d_in[6];
    const float* bw2   = (const float*)d_in[7];
    const float* b2    = (const float*)d_in[8];
    float* out = (float*)d_out;

    float *E1, *E2, *H, *W1p, *W2p, *b1e, *b2e;
    cudaGetSymbolAddress((void**)&E1,  g_E1);
    cudaGetSymbolAddress((void**)&E2,  g_E2);
    cudaGetSymbolAddress((void**)&H,   g_H);
    cudaGetSymbolAddress((void**)&W1p, g_W1p);
    cudaGetSymbolAddress((void**)&W2p, g_W2p);
    cudaGetSymbolAddress((void**)&b1e, g_b1e);
    cudaGetSymbolAddress((void**)&b2e, g_b2e);

    pack_w_kernel<<<(DHID * DIN) / 256, 256>>>(c1, bw1, W1p);
    pack_w_kernel<<<(DOUT * DHID) / 256, 256>>>(c2, bw2, W2p);
    bias_eff_kernel<<<DHID, 128>>>(c1, b1, b1e);
    bias_eff_kernel<<<DOUT, 128>>>(c2, b2, b2e);

    expand1_kernel<<<(BATCH * DIN) / 256, 256>>>(x, E1);
    gemm_tf32_kernel<<<dim3(DHID / 128, BATCH / 128), 256>>>(E1, W1p, b1e, H,
                                                             BATCH, DHID, KDIM);
    ln_silu_expand_kernel<<<BATCH, 256>>>(H, gamma, beta, E2);
    gemm_tf32_kernel<<<dim3(DOUT / 128, BATCH / 128), 256>>>(E2, W2p, b2e, out,
                                                             BATCH, DOUT, KDIM);
}

// round 7
// speedup vs baseline: 1.6329x; 1.6329x over previous
#include <cuda_runtime.h>
#include <cuda_fp16.h>
#include <cstdint>

#define DEV_INLINE __device__ __forceinline__

// tcgen05 only legal in the arch-specific pass; portable pass gets SIMT fallback.
#if defined(__CUDA_ARCH_FEAT_SM103_ALL) || defined(__CUDA_ARCH_FEAT_SM101_ALL) || \
    defined(__CUDA_ARCH_FEAT_SM100_ALL) || defined(__CUDA_ARCH_SPECIFIC__)
#define HAS_TCGEN05 1
#else
#define HAS_TCGEN05 0
#endif

// ---------------- problem sizes ----------------
#define BATCH 16384
#define DIN   1024
#define DHID  1024
#define DOUT  512
#define KDIM  6144          // 6 feature planes x 1024
#define LN_EPSF 1e-5f

// GEMM tiling (fp16 path)
#define BM 128
#define BN 256              // two 128-col TMEM accumulators
#define BK 64               // 64 fp16 = 128 B rows (SW128)

// ---------------- scratch (static device globals; no allocation) ----------------
__device__ __half g_E1[(size_t)BATCH * KDIM];   // expanded features layer1 (fp16)
__device__ __half g_E2[(size_t)BATCH * KDIM];   // expanded features layer2 (fp16)
__device__ float  g_H [(size_t)BATCH * DHID];   // raw layer-1 output (fp32)
__device__ __half g_W1p[(size_t)DHID * KDIM];   // packed weights layer1 (fp16)
__device__ __half g_W2p[(size_t)DOUT * KDIM];   // packed weights layer2 (fp16)
__device__ float  g_b1e[DHID];                  // bias1 + sum_i coeff1[o,i,0]
__device__ float  g_b2e[DOUT];

// ---------------- small helpers ----------------
DEV_INLINE uint32_t smem_u32(const void* p) {
    uint32_t a;
    asm("{ .reg .u64 t; cvta.to.shared.u64 t, %1; cvt.u32.u64 %0, t; }" : "=r"(a) : "l"(p));
    return a;
}
DEV_INLINE float warp_sum(float v) {
#pragma unroll
    for (int o = 16; o > 0; o >>= 1) v += __shfl_xor_sync(0xffffffffu, v, o);
    return v;
}
DEV_INLINE uint32_t sw128(uint32_t off) { return off ^ ((off >> 3) & 0x70); }

#if HAS_TCGEN05
DEV_INLINE uint32_t elect_one() {
    uint32_t p;
    asm volatile("{ .reg .pred p; elect.sync _|p, 0xFFFFFFFF; selp.b32 %0, 1, 0, p; }" : "=r"(p));
    return p;
}

#define MBAR_INIT(addr, cnt) \
    asm volatile("mbarrier.init.shared.b64 [%0], %1;" :: "r"(addr), "r"(cnt) : "memory")

DEV_INLINE void mbar_wait(uint32_t mbar, uint32_t parity) {
    asm volatile(
        "{\n\t.reg .pred P;\n\t"
        "WL_%=:\n\t"
        "mbarrier.try_wait.parity.acquire.cta.shared::cta.b64 P, [%0], %1, 0x989680;\n\t"
        "@P bra WD_%=;\n\t"
        "bra WL_%=;\n\t"
        "WD_%=:\n\t}"
        :: "r"(mbar), "r"(parity) : "memory");
}

#define TCG_ALLOC(smaddr, n) \
    asm volatile("tcgen05.alloc.cta_group::1.sync.aligned.shared::cta.b32 [%0], %1;" \
                 :: "r"(smaddr), "r"(n) : "memory")
#define TCG_RELINQ() \
    asm volatile("tcgen05.relinquish_alloc_permit.cta_group::1.sync.aligned;")
#define TCG_DEALLOC(t, n) \
    asm volatile("tcgen05.dealloc.cta_group::1.sync.aligned.b32 %0, %1;" :: "r"(t), "r"(n))
#define TCG_COMMIT(mb) \
    asm volatile("tcgen05.commit.cta_group::1.mbarrier::arrive::one.shared::cluster.b64 [%0];" \
                 :: "r"(mb) : "memory")
#define TCG_FENCE_AFTER() \
    asm volatile("tcgen05.fence::after_thread_sync;" ::: "memory")
#define TCG_WAIT_LD() \
    asm volatile("tcgen05.wait::ld.sync.aligned;" ::: "memory")
#define FENCE_ASYNC() \
    asm volatile("fence.proxy.async.shared::cta;" ::: "memory")

DEV_INLINE void tmem_ld16(uint32_t* r, uint32_t addr) {
    asm volatile("tcgen05.ld.sync.aligned.32x32b.x16.b32 "
        "{%0,%1,%2,%3,%4,%5,%6,%7,%8,%9,%10,%11,%12,%13,%14,%15}, [%16];"
        : "=r"(r[0]), "=r"(r[1]), "=r"(r[2]), "=r"(r[3]),
          "=r"(r[4]), "=r"(r[5]), "=r"(r[6]), "=r"(r[7]),
          "=r"(r[8]), "=r"(r[9]), "=r"(r[10]), "=r"(r[11]),
          "=r"(r[12]), "=r"(r[13]), "=r"(r[14]), "=r"(r[15])
        : "r"(addr));
}

// fp16 SS MMA, cta_group::1: D[128,128](f32) += A[128,16] * B[128,16]^T
DEV_INLINE void mma_f16_ss(uint32_t d_tmem, uint64_t a_desc, uint64_t b_desc,
                           uint32_t idesc, uint32_t en) {
    asm volatile(
        "{\n\t.reg .pred p;\n\t"
        "setp.ne.u32 p, %5, 0;\n\t"
        "tcgen05.mma.cta_group::1.kind::f16 [%0], %1, %2, %3, {%4,%4,%4,%4}, p;\n\t}"
        :: "r"(d_tmem), "l"(a_desc), "l"(b_desc), "r"(idesc), "r"(0u), "r"(en)
        : "memory");
}

// SW128 K-major SMEM descriptor (layout=2, version=1, SBO=64, LBO=1); the base
// constant is function-local (namespace-scope __device__ constexpr breaks the
// host registration stub when HAS_TCGEN05==0 on the host pass).
DEV_INLINE unsigned long long make_desc(uint32_t smaddr) {
    const unsigned long long base =
        (2ull << 61) | (1ull << 46) | (64ull << 32) | (1ull << 16);
    return base | ((unsigned long long)(smaddr >> 4) & 0x3FFFull);
}
#endif  // HAS_TCGEN05

// ---------------- weight packing (fp16) ----------------
// coeff: [O, 1024, 6] ; bw: [O, 1024] ; Wp: [O, 6144] (plane p = degree p+1, plane 5 = base_w)
__global__ __launch_bounds__(256) void pack_w_kernel(const float* __restrict__ coeff,
                                                     const float* __restrict__ bw,
                                                     __half* __restrict__ Wp) {
    int idx = blockIdx.x * 256 + threadIdx.x;   // o*1024 + i
    int o = idx >> 10, i = idx & 1023;
    const float* c = coeff + (size_t)idx * 6;
    __half* row = Wp + (size_t)o * KDIM;
    row[0 * 1024 + i] = __float2half_rn(c[1]);
    row[1 * 1024 + i] = __float2half_rn(c[2]);
    row[2 * 1024 + i] = __float2half_rn(c[3]);
    row[3 * 1024 + i] = __float2half_rn(c[4]);
    row[4 * 1024 + i] = __float2half_rn(c[5]);
    row[5 * 1024 + i] = __float2half_rn(bw[idx]);
}

// bias_eff[o] = bias[o] + sum_i coeff[o,i,0]   (T0 == 1 contribution)
__global__ __launch_bounds__(128) void bias_eff_kernel(const float* __restrict__ coeff,
                                                       const float* __restrict__ bias,
                                                       float* __restrict__ out) {
    int o = blockIdx.x, tid = threadIdx.x;
    const float* c = coeff + (size_t)o * 1024 * 6;
    float s = 0.f;
    for (int i = tid; i < 1024; i += 128) s += c[(size_t)i * 6];
    s = warp_sum(s);
    __shared__ float red[4];
    if ((tid & 31) == 0) red[tid >> 5] = s;
    __syncthreads();
    if (tid == 0) out[o] = bias[o] + red[0] + red[1] + red[2] + red[3];
}

// ---------------- feature expansion, layer 1 (fp16 out) ----------------
__global__ __launch_bounds__(256) void expand1_kernel(const float* __restrict__ x,
                                                      __half* __restrict__ E) {
    int idx = blockIdx.x * 256 + threadIdx.x;
    int b = idx >> 10, i = idx & 1023;
    float u = tanhf(x[idx]);
    float t = tanhf(u);
    float T2 = 2.f * t * t - 1.f;
    float T3 = 2.f * t * T2 - t;
    float T4 = 2.f * t * T3 - T2;
    float T5 = 2.f * t * T4 - T3;
    __half* row = E + (size_t)b * KDIM;
    row[i]        = __float2half_rn(t);
    row[1024 + i] = __float2half_rn(T2);
    row[2048 + i] = __float2half_rn(T3);
    row[3072 + i] = __float2half_rn(T4);
    row[4096 + i] = __float2half_rn(T5);
    row[5120 + i] = __float2half_rn(u);
}

// ---------------- LayerNorm + SiLU + expansion, layer 2 (fp16 out) ----------------
__global__ __launch_bounds__(256) void ln_silu_expand_kernel(const float* __restrict__ H,
                                                             const float* __restrict__ gamma,
                                                             const float* __restrict__ beta,
                                                             __half* __restrict__ E) {
    int b = blockIdx.x, tid = threadIdx.x;
    int wid = tid >> 5, lane = tid & 31;
    float4 h = ((const float4*)(H + (size_t)b * DHID))[tid];
    float s = h.x + h.y + h.z + h.w;
    float q = h.x * h.x + h.y * h.y + h.z * h.z + h.w * h.w;
    s = warp_sum(s);
    q = warp_sum(q);
    __shared__ float red[16];
    if (lane == 0) { red[wid] = s; red[8 + wid] = q; }
    __syncthreads();
    if (wid == 0) {
        float a = (lane < 8) ? red[lane] : 0.f;
        float c = (lane < 8) ? red[8 + lane] : 0.f;
        a = warp_sum(a);
        c = warp_sum(c);
        if (lane == 0) { red[0] = a; red[1] = c; }
    }
    __syncthreads();
    float mean = red[0] * (1.f / 1024.f);
    float var  = red[1] * (1.f / 1024.f) - mean * mean;
    float rstd = rsqrtf(var + LN_EPSF);
    float4 gv = ((const float4*)gamma)[tid];
    float4 bv = ((const float4*)beta)[tid];
    float hh[4] = {h.x, h.y, h.z, h.w};
    float gg[4] = {gv.x, gv.y, gv.z, gv.w};
    float bb[4] = {bv.x, bv.y, bv.z, bv.w};
    float o1[4], o2[4], o3[4], o4[4], o5[4], o6[4];
#pragma unroll
    for (int j = 0; j < 4; j++) {
        float g  = (hh[j] - mean) * rstd * gg[j] + bb[j];
        float si = g * (1.f / (1.f + __expf(-g)));     // SiLU
        float t  = tanhf(si);
        float T2 = 2.f * t * t - 1.f;
        float T3 = 2.f * t * T2 - t;
        float T4 = 2.f * t * T3 - T2;
        float T5 = 2.f * t * T4 - T3;
        o1[j] = t;  o2[j] = T2; o3[j] = T3; o4[j] = T4; o5[j] = T5; o6[j] = si;
    }
    __half* rowb = E + (size_t)b * KDIM + tid * 4;
#define ST_PLANE(off, o)                                                      \
    do {                                                                      \
        ((__half2*)(rowb + (off)))[0] = __floats2half2_rn((o)[0], (o)[1]);    \
        ((__half2*)(rowb + (off)))[1] = __floats2half2_rn((o)[2], (o)[3]);    \
    } while (0)
    ST_PLANE(0, o1);
    ST_PLANE(1024, o2);
    ST_PLANE(2048, o3);
    ST_PLANE(3072, o4);
    ST_PLANE(4096, o5);
    ST_PLANE(5120, o6);
#undef ST_PLANE
}

// ---------------- GEMM: C[M,N] = A[M,K](fp16) * B[N,K]^T(fp16) + bias ----------------
// sm_103a: fp16 tcgen05, 128x256 tile (2 TMEM accumulators), BK=64,
// 2-stage double-buffered SMEM, SW128 K-major. Dynamic smem:
//   [0,1024)                control (tmem ptr, 2 mbarriers)
//   [1024, +2*16KB)         sA stages (128 x 128B)
//   [.. , +2*32KB)          sB stages (256 x 128B)
#define GEMM_SMEM_BYTES (1024 + 2 * 16384 + 2 * 32768)

#if HAS_TCGEN05
__global__ __launch_bounds__(256) void gemm_f16_kernel(
    const __half* __restrict__ A, const __half* __restrict__ Bw,
    const float* __restrict__ bias, float* __restrict__ C,
    int M, int N, int K) {
    extern __shared__ __align__(1024) char dsm[];
    const uint32_t ctrl  = smem_u32(dsm);
    const uint32_t aBase = ctrl + 1024;
    const uint32_t bBase = ctrl + 1024 + 2 * 16384;

    const int tid = threadIdx.x;
    const int wid = tid >> 5, lane = tid & 31;
    const int m0 = blockIdx.y * BM, n0 = blockIdx.x * BN;

    const uint32_t mbar0 = ctrl + 8, mbar1 = ctrl + 16;
    if (tid == 0) { MBAR_INIT(mbar0, 1); MBAR_INIT(mbar1, 1); }
    if (wid == 0) {
        TCG_ALLOC(ctrl, 256);
        TCG_RELINQ();
    }
    __syncthreads();
    uint32_t tmem;
    asm volatile("ld.shared.b32 %0, [%1];" : "=r"(tmem) : "r"(ctrl));

    // idesc: f32 accum, fp16 A/B (atype=btype=0), N=128, M=128
    const uint32_t IDESC = (1u << 4) | ((128u / 8) << 17) | ((128u / 16) << 24);

    const int KT = K / BK;   // 96
    for (int kt = 0; kt < KT; ++kt) {
        const int s = kt & 1;
        // prefetch this K-tile's global data into registers
        const __half* ga = A  + (size_t)m0 * K + (size_t)kt * BK;
        const __half* gb = Bw + (size_t)n0 * K + (size_t)kt * BK;
        uint4 va[4], vb[8];
#pragma unroll
        for (int p = 0; p < 4; p++) {              // A: 128 rows x 128B
            int idx = tid + p * 256;               // 0..1023
            int r = idx >> 3, c16 = idx & 7;
            va[p] = *(const uint4*)(ga + (size_t)r * K + c16 * 8);
        }
#pragma unroll
        for (int p = 0; p < 8; p++) {              // B: 256 rows x 128B
            int idx = tid + p * 256;               // 0..2047
            int r = idx >> 3, c16 = idx & 7;
            vb[p] = *(const uint4*)(gb + (size_t)r * K + c16 * 8);
        }
        // wait until the MMA from 2 iterations ago is done reading this stage
        if (kt >= 2) mbar_wait(s ? mbar1 : mbar0, ((kt >> 1) - 1) & 1);
#pragma unroll
        for (int p = 0; p < 4; p++) {
            int idx = tid + p * 256;
            int r = idx >> 3, c16 = idx & 7;
            uint32_t off = sw128((uint32_t)((r << 7) + (c16 << 4)));
            *(uint4*)(dsm + 1024 + s * 16384 + off) = va[p];
        }
#pragma unroll
        for (int p = 0; p < 8; p++) {
            int idx = tid + p * 256;
            int r = idx >> 3, c16 = idx & 7;
            uint32_t off = sw128((uint32_t)((r << 7) + (c16 << 4)));
            *(uint4*)(dsm + 1024 + 2 * 16384 + s * 32768 + off) = vb[p];
        }
        __syncthreads();
        if (wid == 0 && elect_one()) {
            FENCE_ASYNC();
            unsigned long long ad = make_desc(aBase + s * 16384);
#pragma unroll
            for (int h = 0; h < 2; h++) {          // two 128-col accumulators
                unsigned long long bd = make_desc(bBase + s * 32768 + h * 16384);
                uint32_t dacc = tmem + (uint32_t)(h * 128);
#pragma unroll
                for (int st = 0; st < 4; st++)     // K=16 per MMA, +32B = +2 units
                    mma_f16_ss(dacc, ad + 2ull * st, bd + 2ull * st, IDESC,
                               (kt > 0) || (st > 0));
            }
            TCG_COMMIT(s ? mbar1 : mbar0);
        }
    }
    // drain both stages' last commits (KT/2 commits each; last completes parity (KT/2-1)&1)
    const uint32_t lastp = ((uint32_t)(KT / 2) - 1u) & 1u;
    mbar_wait(mbar0, lastp);
    mbar_wait(mbar1, lastp);
    TCG_FENCE_AFTER();

    // epilogue: 8 warps. warp w: subpartition w&3 (rows), n-half w>>2 (cols).
    {
        const int sub = wid & 3, half = wid >> 2;
        const int row = m0 + sub * 32 + lane;
        float* crow = C + (size_t)row * N + n0 + half * 128;
        const float* brow = bias + n0 + half * 128;
#pragma unroll 1
        for (int c0 = 0; c0 < 128; c0 += 16) {
            uint32_t r[16];
            tmem_ld16(r, tmem + (uint32_t)(half * 128 + c0));
            TCG_WAIT_LD();
#pragma unroll
            for (int j = 0; j < 4; j++) {
                float4 v;
                v.x = __uint_as_float(r[4 * j + 0]) + __ldg(brow + c0 + 4 * j + 0);
                v.y = __uint_as_float(r[4 * j + 1]) + __ldg(brow + c0 + 4 * j + 1);
                v.z = __uint_as_float(r[4 * j + 2]) + __ldg(brow + c0 + 4 * j + 2);
                v.w = __uint_as_float(r[4 * j + 3]) + __ldg(brow + c0 + 4 * j + 3);
                *(float4*)(crow + c0 + 4 * j) = v;
            }
        }
    }
    __syncthreads();
    if (wid == 0) TCG_DEALLOC(tmem, 256);
}
#else  // ---------------- portable SIMT fallback (never runs with arch cubin) ----------------
__global__ __launch_bounds__(256) void gemm_f16_kernel(
    const __half* __restrict__ A, const __half* __restrict__ Bw,
    const float* __restrict__ bias, float* __restrict__ C,
    int M, int N, int K) {
    extern __shared__ char dsm[];                  // unused; keeps launch cfg identical
    const int tid = threadIdx.x;
    const int m0 = blockIdx.y * BM, n0 = blockIdx.x * BN;
    // 256 threads, each computes 8x8 of a 128x256 tile: 16x32 thread grid? use 8 rows x 32 cols
    const int tx = tid & 31, ty = tid >> 5;        // 32 x 8 threads; micro-tile 16(M) x 8(N)
    float acc[16][8];
#pragma unroll
    for (int i = 0; i < 16; i++)
#pragma unroll
        for (int j = 0; j < 8; j++) acc[i][j] = 0.f;
    for (int k = 0; k < K; k++) {
        float a[16], b[8];
#pragma unroll
        for (int i = 0; i < 16; i++)
            a[i] = __half2float(A[(size_t)(m0 + ty * 16 + i) * K + k]);
#pragma unroll
        for (int j = 0; j < 8; j++)
            b[j] = __half2float(Bw[(size_t)(n0 + tx * 8 + j) * K + k]);
#pragma unroll
        for (int i = 0; i < 16; i++)
#pragma unroll
            for (int j = 0; j < 8; j++) acc[i][j] += a[i] * b[j];
    }
#pragma unroll
    for (int i = 0; i < 16; i++) {
        float* crow = C + (size_t)(m0 + ty * 16 + i) * N + n0 + tx * 8;
#pragma unroll
        for (int j = 0; j < 8; j++) crow[j] = acc[i][j] + bias[n0 + tx * 8 + j];
    }
}
#endif  // HAS_TCGEN05

// ---------------- launch ----------------
extern "C" void kernel_launch(void* const* d_in, const int* in_sizes, int n_in,
                              void* d_out, int out_size) {
    (void)in_sizes; (void)n_in; (void)out_size;
    const float* x     = (const float*)d_in[0];
    const float* c1    = (const float*)d_in[1];
    const float* bw1   = (const float*)d_in[2];
    const float* b1    = (const float*)d_in[3];
    const float* gamma = (const float*)d_in[4];
    const float* beta  = (const float*)d_in[5];
    const float* c2    = (const float*)d_in[6];
    const float* bw2   = (const float*)d_in[7];
    const float* b2    = (const float*)d_in[8];
    float* out = (float*)d_out;

    __half *E1, *E2, *W1p, *W2p;
    float *H, *b1e, *b2e;
    cudaGetSymbolAddress((void**)&E1,  g_E1);
    cudaGetSymbolAddress((void**)&E2,  g_E2);
    cudaGetSymbolAddress((void**)&H,   g_H);
    cudaGetSymbolAddress((void**)&W1p, g_W1p);
    cudaGetSymbolAddress((void**)&W2p, g_W2p);
    cudaGetSymbolAddress((void**)&b1e, g_b1e);
    cudaGetSymbolAddress((void**)&b2e, g_b2e);

    cudaFuncSetAttribute(gemm_f16_kernel,
                         cudaFuncAttributeMaxDynamicSharedMemorySize, GEMM_SMEM_BYTES);

    pack_w_kernel<<<(DHID * DIN) / 256, 256>>>(c1, bw1, W1p);
    pack_w_kernel<<<(DOUT * DHID) / 256, 256>>>(c2, bw2, W2p);
    bias_eff_kernel<<<DHID, 128>>>(c1, b1, b1e);
    bias_eff_kernel<<<DOUT, 128>>>(c2, b2, b2e);

    expand1_kernel<<<(BATCH * DIN) / 256, 256>>>(x, E1);
    gemm_f16_kernel<<<dim3(DHID / BN, BATCH / BM), 256, GEMM_SMEM_BYTES>>>(
        E1, W1p, b1e, H, BATCH, DHID, KDIM);
    ln_silu_expand_kernel<<<BATCH, 256>>>(H, gamma, beta, E2);
    gemm_f16_kernel<<<dim3(DOUT / BN, BATCH / BM), 256, GEMM_SMEM_BYTES>>>(
        E2, W2p, b2e, out, BATCH, DOUT, KDIM);
}